// round 7
// baseline (speedup 1.0000x reference)
#include <cuda_runtime.h>

#define FFT_L   8192
#define NLAYERS 4
#define NSTATE  64
#define NROWS   4096
#define THREADS 512

// ---------------- static device scratch ----------------
__device__ __align__(16) float  g_scratch[(size_t)NROWS * FFT_L];   // ping buffer
__device__ __align__(16) float2 g_tw[FFT_L];                        // W_N^k
__device__ __align__(16) float2 g_kraw[NLAYERS][FFT_L];             // raw K(omega_j)
__device__ __align__(16) float2 g_ke[NLAYERS][FFT_L];               // Hermitian kernel * (1/N), DIGIT-PERMUTED

// ---------------- complex helpers ----------------
__device__ __forceinline__ float2 cmul(float2 a, float2 b) {
    return make_float2(fmaf(a.x, b.x, -a.y * b.y), fmaf(a.x, b.y, a.y * b.x));
}
__device__ __forceinline__ float2 cadd(float2 a, float2 b) { return make_float2(a.x + b.x, a.y + b.y); }
__device__ __forceinline__ float2 csub(float2 a, float2 b) { return make_float2(a.x - b.x, a.y - b.y); }
template <bool INV>
__device__ __forceinline__ float2 mulj(float2 a) {   // * (-i) fwd, * (+i) inv
    return INV ? make_float2(-a.y, a.x) : make_float2(a.y, -a.x);
}
__device__ __forceinline__ float gelu_exact(float v) {
    return 0.5f * v * (1.0f + erff(v * 0.70710678118654752f));
}
// pair-level bank swizzle: P indexes 16B pairs (elements 2P, 2P+1)
__device__ __forceinline__ int swp(int P) { return P ^ ((P >> 3) & 7); }
__device__ __forceinline__ float4 pack2(float2 a, float2 b) {
    return make_float4(a.x, a.y, b.x, b.y);
}

// ---------------- DFT-8 / DFT-16 in registers ----------------
template <bool INV>
__device__ __forceinline__ void dft8(float2 a[8]) {
    const float CC = 0.70710678118654752f;
    float2 s0 = cadd(a[0], a[4]), s1 = csub(a[0], a[4]);
    float2 s2 = cadd(a[2], a[6]), s3 = mulj<INV>(csub(a[2], a[6]));
    float2 E0 = cadd(s0, s2), E2 = csub(s0, s2);
    float2 E1 = cadd(s1, s3), E3 = csub(s1, s3);
    float2 t0 = cadd(a[1], a[5]), t1 = csub(a[1], a[5]);
    float2 t2 = cadd(a[3], a[7]), t3 = mulj<INV>(csub(a[3], a[7]));
    float2 O0 = cadd(t0, t2), O2 = csub(t0, t2);
    float2 O1 = cadd(t1, t3), O3 = csub(t1, t3);
    float2 O1w = INV ? make_float2(CC * (O1.x - O1.y), CC * (O1.x + O1.y))
                     : make_float2(CC * (O1.x + O1.y), CC * (O1.y - O1.x));
    float2 O2w = mulj<INV>(O2);
    float2 O3w = INV ? make_float2(-CC * (O3.x + O3.y), CC * (O3.x - O3.y))
                     : make_float2(CC * (O3.y - O3.x), -CC * (O3.x + O3.y));
    a[0] = cadd(E0, O0);  a[4] = csub(E0, O0);
    a[1] = cadd(E1, O1w); a[5] = csub(E1, O1w);
    a[2] = cadd(E2, O2w); a[6] = csub(E2, O2w);
    a[3] = cadd(E3, O3w); a[7] = csub(E3, O3w);
}

template <bool INV>
__device__ __forceinline__ void dft16(const float2 a[16], float2 X[16]) {
    float2 E[8] = {a[0], a[2], a[4], a[6], a[8], a[10], a[12], a[14]};
    float2 O[8] = {a[1], a[3], a[5], a[7], a[9], a[11], a[13], a[15]};
    dft8<INV>(E);
    dft8<INV>(O);
    const float c1 = 0.9238795325112867f, s1 = 0.3826834323650898f,
                SQ = 0.7071067811865476f;
    const float sg = INV ? 1.0f : -1.0f;
    float2 W[8];
    W[0] = make_float2(1.f, 0.f);
    W[1] = make_float2(c1, sg * s1);
    W[2] = make_float2(SQ, sg * SQ);
    W[3] = make_float2(s1, sg * c1);
    W[4] = make_float2(0.f, sg);
    W[5] = make_float2(-s1, sg * c1);
    W[6] = make_float2(-SQ, sg * SQ);
    W[7] = make_float2(-c1, sg * s1);
#pragma unroll
    for (int k = 0; k < 8; ++k) {
        float2 t = cmul(O[k], W[k]);
        X[k]     = cadd(E[k], t);
        X[k + 8] = csub(E[k], t);
    }
}

// ---------------- prologue kernels ----------------
__global__ void init_tw_kernel() {
    int j = blockIdx.x * blockDim.x + threadIdx.x;
    if (j < FFT_L) {
        float s, c;
        sincospif(-(float)j / (float)(FFT_L / 2), &s, &c);
        g_tw[j] = make_float2(c, s);
    }
}

__global__ void compute_k_kernel(const float* __restrict__ Lr, const float* __restrict__ Li,
                                 const float* __restrict__ P,  const float* __restrict__ B,
                                 const float* __restrict__ Ct, const float* __restrict__ step) {
    int gid = blockIdx.x * blockDim.x + threadIdx.x;
    if (gid >= NLAYERS * FFT_L) return;
    int layer = gid >> 13;
    int j     = gid & (FFT_L - 1);
    const float* lr = Lr + layer * NSTATE;
    const float* li = Li + layer * NSTATE;
    const float* Pp = P  + layer * NSTATE;
    const float* Bp = B  + layer * NSTATE;
    const float* Cp = Ct + layer * NSTATE;
    float st = step[layer];

    float ang = (-6.2831855f * (float)j) / 8192.0f;
    float s, c;
    sincosf(ang, &s, &c);
    float opr = 1.0f + c, opi = s;
    float omr = 1.0f - c, omi = -s;
    float inv_p2 = 1.0f / (opr * opr + opi * opi);
    float qr = (omr * opr + omi * opi) * inv_p2;
    float qi = (omi * opr - omr * opi) * inv_p2;
    float gsc = 2.0f / st;
    float gr = gsc * qr, gi = gsc * qi;
    float cr = 2.0f * opr * inv_p2, ci = -2.0f * opi * inv_p2;

    float k00r = 0.f, k00i = 0.f, k01r = 0.f, k01i = 0.f;
    float k10r = 0.f, k10i = 0.f, k11r = 0.f, k11i = 0.f;
#pragma unroll 8
    for (int n = 0; n < NSTATE; n++) {
        float dr = gr - lr[n];
        float di = gi - li[n];
        float inv = 1.0f / (dr * dr + di * di);
        float ir = dr * inv, ii = -di * inv;
        float b = Bp[n], p = Pp[n], ct = Cp[n];
        float v00 = ct * b, v01 = ct * p, v10 = p * b, v11 = p * p;
        k00r += v00 * ir; k00i += v00 * ii;
        k01r += v01 * ir; k01i += v01 * ii;
        k10r += v10 * ir; k10i += v10 * ii;
        k11r += v11 * ir; k11i += v11 * ii;
    }
    float d1r = 1.0f + k11r, d1i = k11i;
    float invd1 = 1.0f / (d1r * d1r + d1i * d1i);
    float numr = k01r * k10r - k01i * k10i;
    float numi = k01r * k10i + k01i * k10r;
    float qr2 = (numr * d1r + numi * d1i) * invd1;
    float qi2 = (numi * d1r - numr * d1i) * invd1;
    float tr = k00r - qr2, ti = k00i - qi2;
    g_kraw[layer][j] = make_float2(cr * tr - ci * ti, cr * ti + ci * tr);
}

// Hermitian-symmetrize AND permute into DIF digit-reversed order:
// location l holds frequency f = k1 + 8k2 + 64k3 + 512k4 where
// l = 1024k1 + 128k2 + 16k3 + k4.
__global__ void symmetrize_k_kernel() {
    int gid = blockIdx.x * blockDim.x + threadIdx.x;
    if (gid >= NLAYERS * FFT_L) return;
    int layer = gid >> 13;
    int l     = gid & (FFT_L - 1);
    int f = (l >> 10) + (((l >> 7) & 7) << 3) + (((l >> 4) & 7) << 6) + ((l & 15) << 9);
    float2 K1 = g_kraw[layer][f];
    float2 K2 = g_kraw[layer][(FFT_L - f) & (FFT_L - 1)];
    const float sc = 0.5f / (float)FFT_L;   // Hermitian part * 1/N
    g_ke[layer][l] = make_float2((K1.x + K2.x) * sc, (K1.y - K2.y) * sc);
}

// ---------------- in-place DIF forward pass, element stride S (128 or 16) ----------------
// Butterflies u=2t,2t+1 processed as float4 pairs; twiddle W_{8S}^{q*k} applied after DFT.
template <int S>
__device__ __forceinline__ void fwd_pass(float4* __restrict__ Z4, int t) {
    const int TS = 1024 / S;               // g_tw step for W_{8S}
    const int q0 = (2 * t) & (S - 1);      // even
    const int b  = (2 * t) / S;
    const int Pb = b * (4 * S) + (q0 >> 1);
    float2 a[8], c[8];
#pragma unroll
    for (int j = 0; j < 8; ++j) {
        float4 v = Z4[swp(Pb + (S / 2) * j)];
        a[j] = make_float2(v.x, v.y);
        c[j] = make_float2(v.z, v.w);
    }
    dft8<false>(a);
    dft8<false>(c);
    float2 wA1 = g_tw[TS * q0];
    float2 wB1 = g_tw[TS * q0 + TS];
    float2 wA = wA1, wB = wB1;
    Z4[swp(Pb)] = pack2(a[0], c[0]);
    Z4[swp(Pb + (S / 2))] = pack2(cmul(a[1], wA), cmul(c[1], wB));
#pragma unroll
    for (int k = 2; k < 8; ++k) {
        wA = cmul(wA, wA1);
        wB = cmul(wB, wB1);
        Z4[swp(Pb + (S / 2) * k)] = pack2(cmul(a[k], wA), cmul(c[k], wB));
    }
}

// ---------------- in-place DIT inverse pass (transpose of fwd_pass) ----------------
template <int S>
__device__ __forceinline__ void inv_pass(float4* __restrict__ Z4, int t) {
    const int TS = 1024 / S;
    const int q0 = (2 * t) & (S - 1);
    const int b  = (2 * t) / S;
    const int Pb = b * (4 * S) + (q0 >> 1);
    float2 wA1 = g_tw[TS * q0];      wA1.y = -wA1.y;
    float2 wB1 = g_tw[TS * q0 + TS]; wB1.y = -wB1.y;
    float2 a[8], c[8];
    {
        float4 v = Z4[swp(Pb)];
        a[0] = make_float2(v.x, v.y);
        c[0] = make_float2(v.z, v.w);
    }
    float2 wA = wA1, wB = wB1;
    {
        float4 v = Z4[swp(Pb + (S / 2))];
        a[1] = cmul(make_float2(v.x, v.y), wA);
        c[1] = cmul(make_float2(v.z, v.w), wB);
    }
#pragma unroll
    for (int k = 2; k < 8; ++k) {
        wA = cmul(wA, wA1);
        wB = cmul(wB, wB1);
        float4 v = Z4[swp(Pb + (S / 2) * k)];
        a[k] = cmul(make_float2(v.x, v.y), wA);
        c[k] = cmul(make_float2(v.z, v.w), wB);
    }
    dft8<true>(a);
    dft8<true>(c);
#pragma unroll
    for (int j = 0; j < 8; ++j)
        Z4[swp(Pb + (S / 2) * j)] = pack2(a[j], c[j]);
}

// ---------------- fused per-layer kernel ----------------
__global__ void __launch_bounds__(THREADS, 2)
ssm_layer_kernel(const float* __restrict__ in, float* __restrict__ out, int layer) {
    extern __shared__ float4 Z4[];          // single 64 KB in-place buffer

    size_t row = (size_t)blockIdx.x * 2;
    const float* in0 = in + row * FFT_L;
    const float* in1 = in + (row + 1) * FFT_L;
    int t = threadIdx.x;

    // ---- F1: DIF radix-8, S=1024, straight from gmem ----
    {
        float2 a[8], c[8];
#pragma unroll
        for (int j = 0; j < 8; ++j) {
            int e = (t << 1) + (j << 10);
            float2 va = *(const float2*)(in0 + e);
            float2 vb = *(const float2*)(in1 + e);
            a[j] = make_float2(va.x, vb.x);
            c[j] = make_float2(va.y, vb.y);
        }
        dft8<false>(a);
        dft8<false>(c);
        float4 w01 = *(const float4*)&g_tw[t << 1];
        float2 wA1 = make_float2(w01.x, w01.y);
        float2 wB1 = make_float2(w01.z, w01.w);
        float2 wA = wA1, wB = wB1;
        Z4[swp(t)]       = pack2(a[0], c[0]);
        Z4[swp(t + 512)] = pack2(cmul(a[1], wA), cmul(c[1], wB));
#pragma unroll
        for (int k = 2; k < 8; ++k) {
            wA = cmul(wA, wA1);
            wB = cmul(wB, wB1);
            Z4[swp(t + 512 * k)] = pack2(cmul(a[k], wA), cmul(c[k], wB));
        }
    }
    __syncthreads();

    fwd_pass<128>(Z4, t); __syncthreads();
    fwd_pass<16>(Z4, t);  __syncthreads();

    // ---- MID: radix-16 DFT + filter + radix-16 IDFT, all in registers ----
    {
        const float2* __restrict__ ke = g_ke[layer] + (t << 4);
        float2 x[16], X[16];
#pragma unroll
        for (int c = 0; c < 8; ++c) {
            float4 v = Z4[swp((t << 3) + c)];
            x[2 * c]     = make_float2(v.x, v.y);
            x[2 * c + 1] = make_float2(v.z, v.w);
        }
        dft16<false>(x, X);
#pragma unroll
        for (int k = 0; k < 16; ++k) X[k] = cmul(X[k], ke[k]);
        float2 y[16];
        dft16<true>(X, y);
#pragma unroll
        for (int c = 0; c < 8; ++c)
            Z4[swp((t << 3) + c)] = pack2(y[2 * c], y[2 * c + 1]);
    }
    __syncthreads();

    inv_pass<16>(Z4, t);  __syncthreads();
    inv_pass<128>(Z4, t); __syncthreads();

    // ---- I-final: DIT radix-8, S=1024, + residual (gmem re-read) + GELU -> gmem ----
    {
        float4 w01 = *(const float4*)&g_tw[t << 1];
        float2 wA1 = make_float2(w01.x, -w01.y);
        float2 wB1 = make_float2(w01.z, -w01.w);
        float2 a[8], c[8];
        {
            float4 v = Z4[swp(t)];
            a[0] = make_float2(v.x, v.y);
            c[0] = make_float2(v.z, v.w);
        }
        float2 wA = wA1, wB = wB1;
        {
            float4 v = Z4[swp(t + 512)];
            a[1] = cmul(make_float2(v.x, v.y), wA);
            c[1] = cmul(make_float2(v.z, v.w), wB);
        }
#pragma unroll
        for (int k = 2; k < 8; ++k) {
            wA = cmul(wA, wA1);
            wB = cmul(wB, wB1);
            float4 v = Z4[swp(t + 512 * k)];
            a[k] = cmul(make_float2(v.x, v.y), wA);
            c[k] = cmul(make_float2(v.z, v.w), wB);
        }
        dft8<true>(a);
        dft8<true>(c);
        float* o0 = out + row * FFT_L;
        float* o1 = out + (row + 1) * FFT_L;
#pragma unroll
        for (int j = 0; j < 8; ++j) {
            int e = (t << 1) + (j << 10);
            float2 r0 = *(const float2*)(in0 + e);
            float2 r1 = *(const float2*)(in1 + e);
            float2 s0 = make_float2(gelu_exact(a[j].x + r0.x), gelu_exact(c[j].x + r0.y));
            float2 s1 = make_float2(gelu_exact(a[j].y + r1.x), gelu_exact(c[j].y + r1.y));
            *(float2*)(o0 + e) = s0;
            *(float2*)(o1 + e) = s1;
        }
    }
}

// ---------------- launch ----------------
extern "C" void kernel_launch(void* const* d_in, const int* in_sizes, int n_in,
                              void* d_out, int out_size) {
    const float* u  = (const float*)d_in[0];
    const float* Lr = (const float*)d_in[1];
    const float* Li = (const float*)d_in[2];
    const float* P  = (const float*)d_in[3];
    const float* B  = (const float*)d_in[4];
    const float* Ct = (const float*)d_in[5];
    const float* st = (const float*)d_in[6];
    float* out = (float*)d_out;

    float* scratch = nullptr;
    cudaGetSymbolAddress((void**)&scratch, g_scratch);

    const size_t smem_bytes = 4096 * sizeof(float4);   // 64 KB
    cudaFuncSetAttribute(ssm_layer_kernel,
                         cudaFuncAttributeMaxDynamicSharedMemorySize, (int)smem_bytes);

    init_tw_kernel<<<FFT_L / 256, 256>>>();
    compute_k_kernel<<<(NLAYERS * FFT_L) / 256, 256>>>(Lr, Li, P, B, Ct, st);
    symmetrize_k_kernel<<<(NLAYERS * FFT_L) / 256, 256>>>();

    ssm_layer_kernel<<<NROWS / 2, THREADS, smem_bytes>>>(u,       scratch, 0);
    ssm_layer_kernel<<<NROWS / 2, THREADS, smem_bytes>>>(scratch, out,     1);
    ssm_layer_kernel<<<NROWS / 2, THREADS, smem_bytes>>>(out,     scratch, 2);
    ssm_layer_kernel<<<NROWS / 2, THREADS, smem_bytes>>>(scratch, out,     3);
}

// round 8
// speedup vs baseline: 1.2847x; 1.2847x over previous
#include <cuda_runtime.h>

#define FFT_L   8192
#define NLAYERS 4
#define NSTATE  64
#define NROWS   4096
#define THREADS 512

// ---------------- static device scratch ----------------
__device__ __align__(16) float  g_scratch[(size_t)NROWS * FFT_L];   // ping buffer
__device__ __align__(16) float2 g_tw[FFT_L];                        // W_N^k
__device__ __align__(16) float2 g_kraw[NLAYERS][FFT_L];             // raw K(omega_j)
__device__ __align__(16) float2 g_ke[NLAYERS][FFT_L];               // Hermitian kernel * (1/N)

// ---------------- complex helpers ----------------
__device__ __forceinline__ float2 cmul(float2 a, float2 b) {
    return make_float2(fmaf(a.x, b.x, -a.y * b.y), fmaf(a.x, b.y, a.y * b.x));
}
__device__ __forceinline__ float2 cadd(float2 a, float2 b) { return make_float2(a.x + b.x, a.y + b.y); }
__device__ __forceinline__ float2 csub(float2 a, float2 b) { return make_float2(a.x - b.x, a.y - b.y); }
template <bool INV>
__device__ __forceinline__ float2 mulj(float2 a) {   // * (-i) fwd, * (+i) inv
    return INV ? make_float2(-a.y, a.x) : make_float2(a.y, -a.x);
}
__device__ __forceinline__ float gelu_exact(float v) {
    return 0.5f * v * (1.0f + erff(v * 0.70710678118654752f));
}
// pair-level bank swizzle: P indexes 16B pairs (elements 2P, 2P+1)
__device__ __forceinline__ int swp(int P) { return P ^ ((P >> 3) & 7); }
__device__ __forceinline__ float2 ld_elem(const float2* s, int i) {
    return s[(swp(i >> 1) << 1) | (i & 1)];
}
__device__ __forceinline__ float4 pack2(float2 a, float2 b) {
    return make_float4(a.x, a.y, b.x, b.y);
}

// ---------------- DFT-8 / DFT-16 in registers ----------------
template <bool INV>
__device__ __forceinline__ void dft8(float2 a[8]) {
    const float CC = 0.70710678118654752f;
    float2 s0 = cadd(a[0], a[4]), s1 = csub(a[0], a[4]);
    float2 s2 = cadd(a[2], a[6]), s3 = mulj<INV>(csub(a[2], a[6]));
    float2 E0 = cadd(s0, s2), E2 = csub(s0, s2);
    float2 E1 = cadd(s1, s3), E3 = csub(s1, s3);
    float2 t0 = cadd(a[1], a[5]), t1 = csub(a[1], a[5]);
    float2 t2 = cadd(a[3], a[7]), t3 = mulj<INV>(csub(a[3], a[7]));
    float2 O0 = cadd(t0, t2), O2 = csub(t0, t2);
    float2 O1 = cadd(t1, t3), O3 = csub(t1, t3);
    float2 O1w = INV ? make_float2(CC * (O1.x - O1.y), CC * (O1.x + O1.y))
                     : make_float2(CC * (O1.x + O1.y), CC * (O1.y - O1.x));
    float2 O2w = mulj<INV>(O2);
    float2 O3w = INV ? make_float2(-CC * (O3.x + O3.y), CC * (O3.x - O3.y))
                     : make_float2(CC * (O3.y - O3.x), -CC * (O3.x + O3.y));
    a[0] = cadd(E0, O0);  a[4] = csub(E0, O0);
    a[1] = cadd(E1, O1w); a[5] = csub(E1, O1w);
    a[2] = cadd(E2, O2w); a[6] = csub(E2, O2w);
    a[3] = cadd(E3, O3w); a[7] = csub(E3, O3w);
}

template <bool INV>
__device__ __forceinline__ void dft16(const float2 a[16], float2 X[16]) {
    float2 E[8] = {a[0], a[2], a[4], a[6], a[8], a[10], a[12], a[14]};
    float2 O[8] = {a[1], a[3], a[5], a[7], a[9], a[11], a[13], a[15]};
    dft8<INV>(E);
    dft8<INV>(O);
    const float c1 = 0.9238795325112867f, s1 = 0.3826834323650898f,
                SQ = 0.7071067811865476f;
    const float sg = INV ? 1.0f : -1.0f;
    float2 W[8];
    W[0] = make_float2(1.f, 0.f);
    W[1] = make_float2(c1, sg * s1);
    W[2] = make_float2(SQ, sg * SQ);
    W[3] = make_float2(s1, sg * c1);
    W[4] = make_float2(0.f, sg);
    W[5] = make_float2(-s1, sg * c1);
    W[6] = make_float2(-SQ, sg * SQ);
    W[7] = make_float2(-c1, sg * s1);
#pragma unroll
    for (int k = 0; k < 8; ++k) {
        float2 t = cmul(O[k], W[k]);
        X[k]     = cadd(E[k], t);
        X[k + 8] = csub(E[k], t);
    }
}

// ---------------- prologue kernels ----------------
__global__ void init_tw_kernel() {
    int j = blockIdx.x * blockDim.x + threadIdx.x;
    if (j < FFT_L) {
        float s, c;
        sincospif(-(float)j / (float)(FFT_L / 2), &s, &c);
        g_tw[j] = make_float2(c, s);
    }
}

__global__ void compute_k_kernel(const float* __restrict__ Lr, const float* __restrict__ Li,
                                 const float* __restrict__ P,  const float* __restrict__ B,
                                 const float* __restrict__ Ct, const float* __restrict__ step) {
    int gid = blockIdx.x * blockDim.x + threadIdx.x;
    if (gid >= NLAYERS * FFT_L) return;
    int layer = gid >> 13;
    int j     = gid & (FFT_L - 1);
    const float* lr = Lr + layer * NSTATE;
    const float* li = Li + layer * NSTATE;
    const float* Pp = P  + layer * NSTATE;
    const float* Bp = B  + layer * NSTATE;
    const float* Cp = Ct + layer * NSTATE;
    float st = step[layer];

    float ang = (-6.2831855f * (float)j) / 8192.0f;
    float s, c;
    sincosf(ang, &s, &c);
    float opr = 1.0f + c, opi = s;
    float omr = 1.0f - c, omi = -s;
    float inv_p2 = 1.0f / (opr * opr + opi * opi);
    float qr = (omr * opr + omi * opi) * inv_p2;
    float qi = (omi * opr - omr * opi) * inv_p2;
    float gsc = 2.0f / st;
    float gr = gsc * qr, gi = gsc * qi;
    float cr = 2.0f * opr * inv_p2, ci = -2.0f * opi * inv_p2;

    float k00r = 0.f, k00i = 0.f, k01r = 0.f, k01i = 0.f;
    float k10r = 0.f, k10i = 0.f, k11r = 0.f, k11i = 0.f;
#pragma unroll 8
    for (int n = 0; n < NSTATE; n++) {
        float dr = gr - lr[n];
        float di = gi - li[n];
        float inv = 1.0f / (dr * dr + di * di);
        float ir = dr * inv, ii = -di * inv;
        float b = Bp[n], p = Pp[n], ct = Cp[n];
        float v00 = ct * b, v01 = ct * p, v10 = p * b, v11 = p * p;
        k00r += v00 * ir; k00i += v00 * ii;
        k01r += v01 * ir; k01i += v01 * ii;
        k10r += v10 * ir; k10i += v10 * ii;
        k11r += v11 * ir; k11i += v11 * ii;
    }
    float d1r = 1.0f + k11r, d1i = k11i;
    float invd1 = 1.0f / (d1r * d1r + d1i * d1i);
    float numr = k01r * k10r - k01i * k10i;
    float numi = k01r * k10i + k01i * k10r;
    float qr2 = (numr * d1r + numi * d1i) * invd1;
    float qi2 = (numi * d1r - numr * d1i) * invd1;
    float tr = k00r - qr2, ti = k00i - qi2;
    g_kraw[layer][j] = make_float2(cr * tr - ci * ti, cr * ti + ci * tr);
}

__global__ void symmetrize_k_kernel() {
    int gid = blockIdx.x * blockDim.x + threadIdx.x;
    if (gid >= NLAYERS * FFT_L) return;
    int layer = gid >> 13;
    int j     = gid & (FFT_L - 1);
    float2 K1 = g_kraw[layer][j];
    float2 K2 = g_kraw[layer][(FFT_L - j) & (FFT_L - 1)];
    const float sc = 0.5f / (float)FFT_L;   // Hermitian part * 1/N
    g_ke[layer][j] = make_float2((K1.x + K2.x) * sc, (K1.y - K2.y) * sc);
}

// ---------------- T=0 twiddle+store (per-butterfly chains), pairs within butterfly ----------------
template <bool INV>
__device__ __forceinline__ void store0(float4* __restrict__ dst, float2 a[8], float2 b[8], int t) {
    float4 w01 = *(const float4*)&g_tw[t << 1];
    float2 wA1 = make_float2(w01.x, INV ? -w01.y : w01.y);
    float2 wB1 = make_float2(w01.z, INV ? -w01.w : w01.w);
    float2 wA2 = cmul(wA1, wA1), wA3 = cmul(wA2, wA1), wA4 = cmul(wA2, wA2);
    float2 wA5 = cmul(wA4, wA1), wA6 = cmul(wA3, wA3), wA7 = cmul(wA4, wA3);
    float2 wB2 = cmul(wB1, wB1), wB3 = cmul(wB2, wB1), wB4 = cmul(wB2, wB2);
    float2 wB5 = cmul(wB4, wB1), wB6 = cmul(wB3, wB3), wB7 = cmul(wB4, wB3);
    int Pb = t << 3;
    dst[swp(Pb + 0)] = pack2(a[0],            cmul(a[1], wA1));
    dst[swp(Pb + 1)] = pack2(cmul(a[2], wA2), cmul(a[3], wA3));
    dst[swp(Pb + 2)] = pack2(cmul(a[4], wA4), cmul(a[5], wA5));
    dst[swp(Pb + 3)] = pack2(cmul(a[6], wA6), cmul(a[7], wA7));
    dst[swp(Pb + 4)] = pack2(b[0],            cmul(b[1], wB1));
    dst[swp(Pb + 5)] = pack2(cmul(b[2], wB2), cmul(b[3], wB3));
    dst[swp(Pb + 6)] = pack2(cmul(b[4], wB4), cmul(b[5], wB5));
    dst[swp(Pb + 7)] = pack2(cmul(b[6], wB6), cmul(b[7], wB7));
}

// ---------------- generic radix-8 pass for T in {3, 6}: shared twiddle chain ----------------
template <bool INV, int T>
__device__ __forceinline__ void r8_pass(const float4* __restrict__ src,
                                        float4* __restrict__ dst) {
    int t = threadIdx.x;
    float2 a[8], b[8];
#pragma unroll
    for (int j = 0; j < 8; ++j) {
        float4 v = src[swp(t + 512 * j)];
        a[j] = make_float2(v.x, v.y);
        b[j] = make_float2(v.z, v.w);
    }
    dft8<INV>(a);
    dft8<INV>(b);
    int idx = t << 1;
    int pT = idx & ~((1 << T) - 1);
    int qA = idx & ((1 << T) - 1);
    float2 w1 = g_tw[pT];
    if (INV) w1.y = -w1.y;
    float2 w2 = cmul(w1, w1), w3 = cmul(w2, w1), w4 = cmul(w2, w2);
    float2 w5 = cmul(w4, w1), w6 = cmul(w3, w3), w7 = cmul(w4, w3);
    int Pb = (qA >> 1) + (pT << 2);
    const int S = 1 << (T - 1);
    dst[swp(Pb + 0 * S)] = pack2(a[0], b[0]);
    dst[swp(Pb + 1 * S)] = pack2(cmul(a[1], w1), cmul(b[1], w1));
    dst[swp(Pb + 2 * S)] = pack2(cmul(a[2], w2), cmul(b[2], w2));
    dst[swp(Pb + 3 * S)] = pack2(cmul(a[3], w3), cmul(b[3], w3));
    dst[swp(Pb + 4 * S)] = pack2(cmul(a[4], w4), cmul(b[4], w4));
    dst[swp(Pb + 5 * S)] = pack2(cmul(a[5], w5), cmul(b[5], w5));
    dst[swp(Pb + 6 * S)] = pack2(cmul(a[6], w6), cmul(b[6], w6));
    dst[swp(Pb + 7 * S)] = pack2(cmul(a[7], w7), cmul(b[7], w7));
}

// ---------------- fused per-layer kernel ----------------
__global__ void __launch_bounds__(THREADS, 1)
ssm_layer_kernel(const float* __restrict__ in, float* __restrict__ out, int layer) {
    extern __shared__ float4 smem4[];
    float4* X4 = smem4;             // 4096 pairs, swizzled
    float4* Y4 = smem4 + 4096;      // 4096 pairs, swizzled
    float4* U4 = smem4 + 8192;      // residual stash, plain pair layout

    size_t row = (size_t)blockIdx.x * 2;
    const float* in0 = in + row * FFT_L;
    const float* in1 = in + (row + 1) * FFT_L;
    int t = threadIdx.x;

    // ---- F1: radix-8 (T=0) from gmem; stash residual pairs ----
    {
        float2 a[8], b[8];
#pragma unroll
        for (int j = 0; j < 8; ++j) {
            int i = (t << 1) + 1024 * j;
            float2 va = *(const float2*)(in0 + i);
            float2 vb = *(const float2*)(in1 + i);
            a[j] = make_float2(va.x, vb.x);
            b[j] = make_float2(va.y, vb.y);
            U4[t + 512 * j] = make_float4(va.x, vb.x, va.y, vb.y);
        }
        dft8<false>(a);
        dft8<false>(b);
        store0<false>(X4, a, b, t);
    }
    __syncthreads();

    r8_pass<false, 3>(X4, Y4); __syncthreads();
    r8_pass<false, 6>(Y4, X4); __syncthreads();

    // ---- FUSED: F4 (radix-16) -> filter -> I1 (two inverse radix-8, T=0) in regs ----
    {
        const float2* Xs = (const float2*)X4;
        const float2* __restrict__ ke = g_ke[layer];
        float2 a[16], S[16];
#pragma unroll
        for (int j = 0; j < 16; ++j) a[j] = ld_elem(Xs, t + (j << 9));
        dft16<false>(a, S);
        // filter: thread t holds spectrum at frequencies t + 512k
#pragma unroll
        for (int k = 0; k < 16; ++k) S[k] = cmul(S[k], ke[t + (k << 9)]);
        // inverse T=0 butterflies idx=t (even k) and idx=t+512 (odd k)
        float2 ai[8], bi[8];
#pragma unroll
        for (int j = 0; j < 8; ++j) {
            ai[j] = S[2 * j];
            bi[j] = S[2 * j + 1];
        }
        dft8<true>(ai);
        dft8<true>(bi);
        // store with conjugate twiddle chains: dst[8*idx + k] *= conj(W^{idx*k})
        float2 wA1 = g_tw[t];       wA1.y = -wA1.y;        // idx = t
        float2 wB1 = g_tw[t + 512]; wB1.y = -wB1.y;        // idx = t + 512
        float2 wA2 = cmul(wA1, wA1), wA3 = cmul(wA2, wA1), wA4 = cmul(wA2, wA2);
        float2 wA5 = cmul(wA4, wA1), wA6 = cmul(wA3, wA3), wA7 = cmul(wA4, wA3);
        float2 wB2 = cmul(wB1, wB1), wB3 = cmul(wB2, wB1), wB4 = cmul(wB2, wB2);
        float2 wB5 = cmul(wB4, wB1), wB6 = cmul(wB3, wB3), wB7 = cmul(wB4, wB3);
        int Pa = t << 2;               // pairs for elements 8t .. 8t+7
        Y4[swp(Pa + 0)] = pack2(ai[0],            cmul(ai[1], wA1));
        Y4[swp(Pa + 1)] = pack2(cmul(ai[2], wA2), cmul(ai[3], wA3));
        Y4[swp(Pa + 2)] = pack2(cmul(ai[4], wA4), cmul(ai[5], wA5));
        Y4[swp(Pa + 3)] = pack2(cmul(ai[6], wA6), cmul(ai[7], wA7));
        int Pb = Pa + 2048;            // pairs for elements 8(t+512) .. +7
        Y4[swp(Pb + 0)] = pack2(bi[0],            cmul(bi[1], wB1));
        Y4[swp(Pb + 1)] = pack2(cmul(bi[2], wB2), cmul(bi[3], wB3));
        Y4[swp(Pb + 2)] = pack2(cmul(bi[4], wB4), cmul(bi[5], wB5));
        Y4[swp(Pb + 3)] = pack2(cmul(bi[6], wB6), cmul(bi[7], wB7));
    }
    __syncthreads();

    r8_pass<true, 3>(Y4, X4); __syncthreads();
    r8_pass<true, 6>(X4, Y4); __syncthreads();

    // ---- I4: final radix-16 + residual + GELU, straight to gmem ----
    {
        const float2* Ys = (const float2*)Y4;
        const float2* Ue = (const float2*)U4;   // plain layout: element i at [i]
        float* o0 = out + row * FFT_L;
        float* o1 = out + (row + 1) * FFT_L;
        float2 a[16], Xo[16];
#pragma unroll
        for (int j = 0; j < 16; ++j) a[j] = ld_elem(Ys, t + (j << 9));
        dft16<true>(a, Xo);
#pragma unroll
        for (int k = 0; k < 16; ++k) {
            int i = t + (k << 9);
            float2 u = Ue[i];
            o0[i] = gelu_exact(Xo[k].x + u.x);
            o1[i] = gelu_exact(Xo[k].y + u.y);
        }
    }
}

// ---------------- launch ----------------
extern "C" void kernel_launch(void* const* d_in, const int* in_sizes, int n_in,
                              void* d_out, int out_size) {
    const float* u  = (const float*)d_in[0];
    const float* Lr = (const float*)d_in[1];
    const float* Li = (const float*)d_in[2];
    const float* P  = (const float*)d_in[3];
    const float* B  = (const float*)d_in[4];
    const float* Ct = (const float*)d_in[5];
    const float* st = (const float*)d_in[6];
    float* out = (float*)d_out;

    float* scratch = nullptr;
    cudaGetSymbolAddress((void**)&scratch, g_scratch);

    const size_t smem_bytes = 3 * 4096 * sizeof(float4);   // 192 KB
    cudaFuncSetAttribute(ssm_layer_kernel,
                         cudaFuncAttributeMaxDynamicSharedMemorySize, (int)smem_bytes);

    init_tw_kernel<<<FFT_L / 256, 256>>>();
    compute_k_kernel<<<(NLAYERS * FFT_L) / 256, 256>>>(Lr, Li, P, B, Ct, st);
    symmetrize_k_kernel<<<(NLAYERS * FFT_L) / 256, 256>>>();

    ssm_layer_kernel<<<NROWS / 2, THREADS, smem_bytes>>>(u,       scratch, 0);
    ssm_layer_kernel<<<NROWS / 2, THREADS, smem_bytes>>>(scratch, out,     1);
    ssm_layer_kernel<<<NROWS / 2, THREADS, smem_bytes>>>(out,     scratch, 2);
    ssm_layer_kernel<<<NROWS / 2, THREADS, smem_bytes>>>(scratch, out,     3);
}